// round 1
// baseline (speedup 1.0000x reference)
#include <cuda_runtime.h>
#include <math.h>

#define D 256
#define HALF_D 128
#define MAXN 4096
#define MAXROWS 16384

// ---- device scratch (no allocations allowed) ----
__device__ float g_M [D*D];   // sparse skew matrix, dense form: M[r][c]=+s, M[c][r]=-s
__device__ float g_M2[D*D];   // M^2
__device__ float g_S [D*D];   // Horner accumulators
__device__ float g_T [D*D];
__device__ float g_G [D*D];   // G = R - I,  R = (I+M)(I-M^2)^{-1}(I+M)
__device__ float2 g_cs[MAXN*HALF_D]; // (cos, sin) table per (position, freq)
__device__ float g_H [MAXROWS*D];    // rope'd H = [q_r ; k_r]

// ---------------- prep kernels ----------------

__global__ void k_zeroM() {
    int i = blockIdx.x * blockDim.x + threadIdx.x;
    if (i < D*D) g_M[i] = 0.f;
}

__global__ void k_scatter(const int* __restrict__ rows, const int* __restrict__ cols,
                          const float* __restrict__ s, int E) {
    int e = blockIdx.x * blockDim.x + threadIdx.x;
    if (e < E) {
        int r = rows[e], c = cols[e];
        float v = s[e];
        g_M[r*D + c] =  v;
        g_M[c*D + r] = -v;
    }
}

__global__ void k_seed() { // S = I + M2
    int i = blockIdx.x, j = threadIdx.x;
    g_S[i*D + j] = g_M2[i*D + j] + ((i == j) ? 1.f : 0.f);
}

// Small dense 256x256 matmul; 'which' selects operands from device globals
// (avoids host-side symbol lookups inside graph capture).
//  0: M2 = M*M
//  1: T  = I + M2*S
//  2: S  = I + M2*T
//  3: T  = S + M*S          (T = (I+M)*S)
//  4: G  = T*M + T - I      (G = R - I)
__global__ void __launch_bounds__(D) k_dmm(int which) {
    __shared__ float a[D];
    const float *A, *Bm, *add = nullptr;
    float *out; int plusI = 0;
    switch (which) {
        case 0: A = g_M;  Bm = g_M; out = g_M2;               break;
        case 1: A = g_M2; Bm = g_S; out = g_T;  plusI =  1;   break;
        case 2: A = g_M2; Bm = g_T; out = g_S;  plusI =  1;   break;
        case 3: A = g_M;  Bm = g_S; out = g_T;  add = g_S;    break;
        default:A = g_T;  Bm = g_M; out = g_G;  add = g_T; plusI = -1; break;
    }
    int i = blockIdx.x, j = threadIdx.x;
    a[j] = A[i*D + j];
    __syncthreads();
    float acc = 0.f;
    #pragma unroll 16
    for (int k = 0; k < D; k++) acc = fmaf(a[k], Bm[k*D + j], acc);
    if (add) acc += add[i*D + j];
    if (plusI && i == j) acc += (float)plusI;
    out[i*D + j] = acc;
}

// cos/sin table. Match the reference: angle is rounded to fp32 FIRST
// (pos_f32 * freq_f32), then the precise sin/cos of that fp32 value.
// Exact range reduction is done in double so MUFU stays accurate regardless
// of compiler fast-math settings.
__global__ void k_table(const int* __restrict__ pos, const float* __restrict__ freqs, int N) {
    int idx = blockIdx.x * blockDim.x + threadIdx.x;
    if (idx >= N * HALF_D) return;
    int n = idx >> 7;          // / 128
    int j = idx & (HALF_D-1);
    float ang = (float)pos[n] * freqs[j];          // fp32, same rounding as ref
    double a  = (double)ang;
    double qd = rint(a * 0.15915494309189535);     // 1/(2*pi)
    double rd = a - qd * 6.283185307179586477;     // exact-enough reduction
    float rf  = (float)rd;                          // in [-pi, pi]
    g_cs[idx] = make_float2(__cosf(rf), __sinf(rf));
}

// RoPE both q and k into the staging buffer g_H (row-major 16384 x 256).
__global__ void k_rope(const float* __restrict__ q, const float* __restrict__ k,
                       int BN, int N) {
    int idx = blockIdx.x * blockDim.x + threadIdx.x;   // pair index
    int g = idx >> 7;          // row in H
    int j = idx & (HALF_D-1);  // pair
    if (g >= 2*BN) return;
    const float* src; int n;
    if (g < BN) { src = q + (size_t)g*D;      n = g % N; }
    else        { src = k + (size_t)(g-BN)*D; n = (g-BN) % N; }
    float2 xy = *(const float2*)(src + 2*j);
    float2 cs = g_cs[n*HALF_D + j];
    float2 o;
    o.x = xy.x*cs.x - xy.y*cs.y;
    o.y = xy.x*cs.y + xy.y*cs.x;
    *(float2*)(g_H + (size_t)g*D + 2*j) = o;
}

// out = H + H*G.  One block = 32 rows x all 256 cols; thread t owns column t.
// A-tile in shared (broadcast reads), G streamed from L2 (256KB, hot).
__global__ void __launch_bounds__(D) k_gemm(float* __restrict__ out) {
    __shared__ float As[32][D];
    int row0 = blockIdx.x * 32;
    int j = threadIdx.x;
    #pragma unroll
    for (int r = 0; r < 32; r++)
        As[r][j] = g_H[(size_t)(row0 + r)*D + j];
    __syncthreads();

    float acc[32];
    #pragma unroll
    for (int r = 0; r < 32; r++) acc[r] = 0.f;

    for (int kc = 0; kc < D; kc += 8) {
        float gg[8];
        #pragma unroll
        for (int u = 0; u < 8; u++) gg[u] = g_G[(kc + u)*D + j];
        #pragma unroll
        for (int r = 0; r < 32; r++) {
            float4 a0 = *(const float4*)&As[r][kc];
            float4 a1 = *(const float4*)&As[r][kc + 4];
            float s = acc[r];
            s = fmaf(a0.x, gg[0], s); s = fmaf(a0.y, gg[1], s);
            s = fmaf(a0.z, gg[2], s); s = fmaf(a0.w, gg[3], s);
            s = fmaf(a1.x, gg[4], s); s = fmaf(a1.y, gg[5], s);
            s = fmaf(a1.z, gg[6], s); s = fmaf(a1.w, gg[7], s);
            acc[r] = s;
        }
    }
    #pragma unroll
    for (int r = 0; r < 32; r++)
        out[(size_t)(row0 + r)*D + j] = As[r][j] + acc[r];
}

// ---------------- launcher ----------------
extern "C" void kernel_launch(void* const* d_in, const int* in_sizes, int n_in,
                              void* d_out, int out_size) {
    const float* q     = (const float*)d_in[0];
    const float* k     = (const float*)d_in[1];
    const float* freqs = (const float*)d_in[2];
    const float* sp    = (const float*)d_in[3];
    const int*   pos   = (const int*)  d_in[4];
    const int*   rows  = (const int*)  d_in[5];
    const int*   cols  = (const int*)  d_in[6];
    float* out = (float*)d_out;

    int E    = in_sizes[3];
    int N    = in_sizes[4];
    int BN   = in_sizes[0] / D;   // rows of q (= B*N)
    int ROWS = 2 * BN;

    // Build dense skew M
    k_zeroM<<<(D*D + 1023)/1024, 1024>>>();
    k_scatter<<<(E + 255)/256, 256>>>(rows, cols, sp, E);

    // G = (I+M)(I + M^2 + M^4 + M^6 + M^8 + M^10)(I+M) - I   (Horner in M^2)
    k_dmm<<<D, D>>>(0);   // M2 = M*M
    k_seed<<<D, D>>>();   // S = I + M2
    k_dmm<<<D, D>>>(1);   // T = I + M2*S      (.. + M^4)
    k_dmm<<<D, D>>>(2);   // S = I + M2*T      (.. + M^6)
    k_dmm<<<D, D>>>(1);   // T = I + M2*S      (.. + M^8)
    k_dmm<<<D, D>>>(2);   // S = I + M2*T      (.. + M^10)
    k_dmm<<<D, D>>>(3);   // T = (I+M)*S
    k_dmm<<<D, D>>>(4);   // G = T*M + T - I

    // RoPE
    k_table<<<(N*HALF_D + 255)/256, 256>>>(pos, freqs, N);
    k_rope<<<(ROWS*HALF_D + 255)/256, 256>>>(q, k, BN, N);

    // out = H + H*G
    k_gemm<<<ROWS/32, D>>>(out);
}

// round 2
// speedup vs baseline: 1.4172x; 1.4172x over previous
#include <cuda_runtime.h>
#include <math.h>

#define D 256
#define HALF_D 128
#define MAXN 4096
#define MAXROWS 16384

// ---- device scratch (module-load zero-initialized; no allocations) ----
__device__ float g_M [D*D];   // dense skew: M[r][c]=+s, M[c][r]=-s (non-edges stay 0 forever)
__device__ float g_M2[D*D];
__device__ float g_M4[D*D];
__device__ float g_S [D*D];   // S = (I+M^2)(I+M^4)  ~= (I - M^2)^{-1}
__device__ float g_T [D*D];   // T = (I+M) S
__device__ float g_G [D*D];   // G = T(I+M) - I  = R - I
__device__ float2 g_cs[MAXN*HALF_D]; // (cos,sin) per (position, freq-pair)

// packed-f32x2 helpers (Blackwell f32x2 pipe, PTX-only)
#define FMA2(d, a, b) asm("fma.rn.f32x2 %0, %1, %2, %0;" : "+l"(d) : "l"(a), "l"(b))
#define DUP2(d, f)    asm("mov.b64 %0, {%1, %1};" : "=l"(d) : "r"(__float_as_uint(f)))

// ---------------- fused front: edge scatter + cos/sin table ----------------
__global__ void k_front(const int* __restrict__ rows, const int* __restrict__ cols,
                        const float* __restrict__ s, int E,
                        const int* __restrict__ pos, const float* __restrict__ freqs, int N) {
    int idx = blockIdx.x * blockDim.x + threadIdx.x;
    int tableN = N * HALF_D;
    if (idx < tableN) {
        int n = idx >> 7, j = idx & (HALF_D - 1);
        float ang = (float)pos[n] * freqs[j];          // fp32 rounding matches ref
        double a  = (double)ang;                       // exact range reduction
        double qd = rint(a * 0.15915494309189535);
        double rd = a - qd * 6.283185307179586477;
        float rf  = (float)rd;
        g_cs[idx] = make_float2(__cosf(rf), __sinf(rf));
    } else {
        int e = idx - tableN;
        if (e < E) {
            int r = rows[e], c = cols[e];
            float v = s[e];
            g_M[r*D + c] =  v;     // idempotent each replay
            g_M[c*D + r] = -v;
        }
    }
}

// ---------------- small dense 256x256 matmuls (Cayley prep chain) ----------------
//  0: M2 = M*M
//  1: M4 = M2*M2
//  2: S  = M2*M4 + M2 + M4 + I     ( = (I+M2)(I+M4) )
//  3: T  = M*S + S                 ( = (I+M) S )
//  4: G  = T*M + T - I             ( = (I+M)S(I+M) - I = R - I )
__global__ void __launch_bounds__(D) k_dmm(int which) {
    __shared__ float a[D];
    const float *A, *Bm, *add1 = nullptr, *add2 = nullptr;
    float *outp; float plusI = 0.f;
    switch (which) {
        case 0: A = g_M;  Bm = g_M;  outp = g_M2; break;
        case 1: A = g_M2; Bm = g_M2; outp = g_M4; break;
        case 2: A = g_M2; Bm = g_M4; outp = g_S; add1 = g_M2; add2 = g_M4; plusI =  1.f; break;
        case 3: A = g_M;  Bm = g_S;  outp = g_T; add1 = g_S;  break;
        default:A = g_T;  Bm = g_M;  outp = g_G; add1 = g_T;  plusI = -1.f; break;
    }
    int i = blockIdx.x, j = threadIdx.x;
    a[j] = A[i*D + j];
    __syncthreads();
    float acc = 0.f;
    #pragma unroll 16
    for (int k = 0; k < D; k++) acc = fmaf(a[k], Bm[k*D + j], acc);
    if (add1) acc += add1[i*D + j];
    if (add2) acc += add2[i*D + j];
    if (plusI != 0.f && i == j) acc += plusI;
    outp[i*D + j] = acc;
}

// ---------------- main GEMM: out = H + H*G, RoPE fused into A-tile load ----------------
// Block: 256 threads, tile 16 rows x 256 cols. Accumulators packed over ROW PAIRS
// in f32x2; G scalar duplicated once per (k, col).
__global__ void __launch_bounds__(256) k_gemm(const float* __restrict__ q,
                                              const float* __restrict__ kk,
                                              float* __restrict__ out,
                                              int BN, int N) {
    __shared__ __align__(16) float2 As2[8][D];   // [rowpair p][k] = (row 2p, row 2p+1)
    int t = threadIdx.x;
    int row0 = blockIdx.x * 16;

    // Fill A-tile with RoPE applied on the fly (no g_H staging buffer).
    for (int idx = t; idx < 16 * HALF_D; idx += 256) {
        int r  = idx >> 7;          // 0..15 (row within tile)
        int jp = idx & (HALF_D-1);  // rotation pair 0..127
        int row = row0 + r;
        const float* src; int n;
        if (row < BN) { src = q  + (size_t)row*D;      n = row % N; }
        else          { src = kk + (size_t)(row-BN)*D; n = (row-BN) % N; }
        float2 v  = *(const float2*)(src + 2*jp);
        float2 cs = g_cs[n*HALF_D + jp];
        float e = v.x*cs.x - v.y*cs.y;     // element 2*jp
        float o = v.x*cs.y + v.y*cs.x;     // element 2*jp+1
        float* As2f = (float*)As2;
        int base = ((r >> 1)*D + 2*jp)*2 + (r & 1);
        As2f[base]     = e;
        As2f[base + 2] = o;
    }
    __syncthreads();

    int cg = t & 127;          // column group (2 cols)
    int rg = t >> 7;           // row group (8 rows)
    int j0 = cg * 2;
    int p0 = rg * 4;           // first rowpair of this thread

    unsigned long long acc[4][2];
    #pragma unroll
    for (int pp = 0; pp < 4; pp++) { acc[pp][0] = 0ull; acc[pp][1] = 0ull; }

    #pragma unroll 8
    for (int k = 0; k < D; k += 2) {
        float2 gk0 = *(const float2*)&g_G[(size_t)k*D + j0];
        float2 gk1 = *(const float2*)&g_G[(size_t)(k+1)*D + j0];
        unsigned long long g00, g01, g10, g11;
        DUP2(g00, gk0.x); DUP2(g01, gk0.y);
        DUP2(g10, gk1.x); DUP2(g11, gk1.y);
        ulonglong2 Ap[4];
        #pragma unroll
        for (int pp = 0; pp < 4; pp++)
            Ap[pp] = *(const ulonglong2*)&As2[p0 + pp][k];   // (a2[k], a2[k+1])
        #pragma unroll
        for (int pp = 0; pp < 4; pp++) {
            FMA2(acc[pp][0], Ap[pp].x, g00);
            FMA2(acc[pp][1], Ap[pp].x, g01);
            FMA2(acc[pp][0], Ap[pp].y, g10);
            FMA2(acc[pp][1], Ap[pp].y, g11);
        }
    }

    // Epilogue: out = H + correction  (acc packed over (even,odd) rows)
    #pragma unroll
    for (int pp = 0; pp < 4; pp++) {
        int p  = p0 + pp;
        int re = row0 + 2*p;
        #pragma unroll
        for (int c = 0; c < 2; c++) {
            float2 h = As2[p][j0 + c];
            unsigned long long a = acc[pp][c];
            float lo = __uint_as_float((unsigned)a);
            float hi = __uint_as_float((unsigned)(a >> 32));
            out[(size_t)re*D     + j0 + c] = h.x + lo;
            out[(size_t)(re+1)*D + j0 + c] = h.y + hi;
        }
    }
}

// ---------------- launcher: 7 launches total ----------------
extern "C" void kernel_launch(void* const* d_in, const int* in_sizes, int n_in,
                              void* d_out, int out_size) {
    const float* q     = (const float*)d_in[0];
    const float* k     = (const float*)d_in[1];
    const float* freqs = (const float*)d_in[2];
    const float* sp    = (const float*)d_in[3];
    const int*   pos   = (const int*)  d_in[4];
    const int*   rows  = (const int*)  d_in[5];
    const int*   cols  = (const int*)  d_in[6];
    float* out = (float*)d_out;

    int E    = in_sizes[3];
    int N    = in_sizes[4];
    int BN   = in_sizes[0] / D;   // rows of q (= B*N)
    int ROWS = 2 * BN;

    int frontWork = N*HALF_D + E;
    k_front<<<(frontWork + 255)/256, 256>>>(rows, cols, sp, E, pos, freqs, N);

    k_dmm<<<D, D>>>(0);   // M2
    k_dmm<<<D, D>>>(1);   // M4
    k_dmm<<<D, D>>>(2);   // S = (I+M2)(I+M4)
    k_dmm<<<D, D>>>(3);   // T = (I+M)S
    k_dmm<<<D, D>>>(4);   // G = T(I+M) - I

    k_gemm<<<ROWS/16, 256>>>(q, k, out, BN, N);
}